// round 11
// baseline (speedup 1.0000x reference)
#include <cuda_runtime.h>
#include <cstddef>

#define B_   32
#define T_   2048
#define E_   128
#define G_   4              // CTAs per batch
#define ROWS 512            // T_ / G_  rows per CTA
#define NW   32             // warps per CTA
#define RPW  16             // rows per warp
#define NCTA (B_ * G_)      // 128 CTAs, all co-resident (<=148 SMs)
#define CPT  16             // t's per CTA in phase C (T_/NCTA)
#define EP   (E_ + 4)       // padded c row (bank-conflict-free)
#define INV_T (1.0f / 2048.0f)

// ---------------- scratch (device globals; zero-init; no allocation) -------
__device__ float  g_s_part[2][B_][G_][E_];
__device__ float  g_c_part[2][B_][G_][E_];
__device__ float  g_d[2][B_][T_];
__device__ float  g_et[2][B_][T_];
__device__ float2 g_stats[2][B_][NCTA];    // per-16t-chunk (max, sumexp)
__device__ float  g_o_part[2][B_][G_][E_];
__device__ unsigned g_barA[B_];            // per-batch, after phase A
__device__ unsigned g_barG[2];             // global, after B and after C
__device__ unsigned g_barD[B_];            // per-batch, after phase D partials
__device__ unsigned g_tick;                // reset ticket

static __device__ __forceinline__ float dot4(float4 a, float4 b) {
    return fmaf(a.x, b.x, fmaf(a.y, b.y, fmaf(a.z, b.z, a.w * b.w)));
}

// spin barrier (per-batch target=G_, global target=NCTA); co-residency makes it safe
static __device__ __forceinline__ void spin_bar(unsigned* cnt, unsigned target) {
    __threadfence();
    __syncthreads();
    if (threadIdx.x == 0) {
        atomicAdd(cnt, 1u);
        while (*(volatile unsigned*)cnt < target) __nanosleep(32);
        __threadfence();
    }
    __syncthreads();
}

// ===========================================================================
__global__ void __launch_bounds__(1024, 1) fused_attn(
    const float* __restrict__ x1, const float* __restrict__ x2,
    const float* __restrict__ W1, const float* __restrict__ bb1,
    const float* __restrict__ U1, const float* __restrict__ W2,
    const float* __restrict__ bb2, const float* __restrict__ U2,
    float* __restrict__ out)
{
    const int b    = blockIdx.x >> 2;
    const int g    = blockIdx.x & 3;
    const int ci   = blockIdx.x;         // phase-C global t-chunk id
    const int tid  = threadIdx.x;
    const int lane = tid & 31;
    const int w    = tid >> 5;
    const int t0   = g * ROWS;
    const int rbase = w * RPW;

    // sred (32KB, phases A/B/D) and csh (33KB, phase C) never coexist: union
    __shared__ __align__(16) unsigned char u_buf[B_ * 2 * EP * 4];
    float4 (*sred)[32] = reinterpret_cast<float4 (*)[32]>(u_buf);     // [2*NW][32]
    float  (*csh)[2][EP] = reinterpret_cast<float (*)[2][EP]>(u_buf); // [B_][2][EP]
    __shared__ float vsh[2][E_];
    __shared__ float tsh[2][ROWS];
    __shared__ float s_m[2], s_iz[2];

    const float4* p1 = (const float4*)(x1 + ((size_t)b * T_ + t0) * E_);
    const float4* p2 = (const float4*)(x2 + ((size_t)b * T_ + t0) * E_);

    // ================= Phase A: column sums + row dots d ===================
    {
        float4 w1l = ((const float4*)W1)[lane];
        float4 w2l = ((const float4*)W2)[lane];
        float4 s1a = {0,0,0,0}, s2a = {0,0,0,0};
        #pragma unroll
        for (int r4 = 0; r4 < RPW; r4 += 4) {
            float4 v1[4], v2[4];
            #pragma unroll
            for (int k = 0; k < 4; k++) {
                v1[k] = __ldg(p1 + (rbase + r4 + k) * 32 + lane);
                v2[k] = __ldg(p2 + (rbase + r4 + k) * 32 + lane);
            }
            float d1[4], d2[4];
            #pragma unroll
            for (int k = 0; k < 4; k++) {
                s1a.x += v1[k].x; s1a.y += v1[k].y; s1a.z += v1[k].z; s1a.w += v1[k].w;
                s2a.x += v2[k].x; s2a.y += v2[k].y; s2a.z += v2[k].z; s2a.w += v2[k].w;
                d1[k] = dot4(v1[k], w1l);
                d2[k] = dot4(v2[k], w2l);
            }
            #pragma unroll
            for (int off = 16; off; off >>= 1) {
                #pragma unroll
                for (int k = 0; k < 4; k++) {
                    d1[k] += __shfl_xor_sync(0xffffffffu, d1[k], off);
                    d2[k] += __shfl_xor_sync(0xffffffffu, d2[k], off);
                }
            }
            if (lane == 0) {
                #pragma unroll
                for (int k = 0; k < 4; k++) {
                    g_d[0][b][t0 + rbase + r4 + k] = d1[k];
                    g_d[1][b][t0 + rbase + r4 + k] = d2[k];
                }
            }
        }
        sred[w][lane] = s1a;
        sred[NW + w][lane] = s2a;
        __syncthreads();
        if (tid < 64) {
            int ti = tid >> 5;
            float4 s = sred[ti * NW][lane];
            #pragma unroll
            for (int k = 1; k < NW; k++) {
                float4 v = sred[ti * NW + k][lane];
                s.x += v.x; s.y += v.y; s.z += v.z; s.w += v.w;
            }
            ((float4*)&g_s_part[ti][b][g][0])[lane] = s;
        }
    }
    spin_bar(&g_barA[b], G_);

    if (tid < 256) {
        int ti = tid >> 7, e = tid & 127;
        float acc = 0.f;
        #pragma unroll
        for (int gg = 0; gg < G_; gg++) acc += g_s_part[ti][b][gg][e];
        vsh[ti][e] = acc;
    }
    __syncthreads();

    // ================= Phase B: c partials (x rows L2-hot) =================
    {
        float4 s1l = ((const float4*)vsh[0])[lane];
        float4 s2l = ((const float4*)vsh[1])[lane];
        float4 c1a = {0,0,0,0}, c2a = {0,0,0,0};
        #pragma unroll
        for (int r4 = 0; r4 < RPW; r4 += 4) {
            float4 v1[4], v2[4];
            #pragma unroll
            for (int k = 0; k < 4; k++) {
                v1[k] = __ldg(p1 + (rbase + r4 + k) * 32 + lane);
                v2[k] = __ldg(p2 + (rbase + r4 + k) * 32 + lane);
            }
            float a1[4], a2[4];
            #pragma unroll
            for (int k = 0; k < 4; k++) {
                a1[k] = dot4(v1[k], s2l);   // x1 . s2
                a2[k] = dot4(v2[k], s1l);   // x2 . s1
            }
            #pragma unroll
            for (int off = 16; off; off >>= 1) {
                #pragma unroll
                for (int k = 0; k < 4; k++) {
                    a1[k] += __shfl_xor_sync(0xffffffffu, a1[k], off);
                    a2[k] += __shfl_xor_sync(0xffffffffu, a2[k], off);
                }
            }
            #pragma unroll
            for (int k = 0; k < 4; k++) {
                c1a.x = fmaf(a1[k], v2[k].x, c1a.x); c1a.y = fmaf(a1[k], v2[k].y, c1a.y);
                c1a.z = fmaf(a1[k], v2[k].z, c1a.z); c1a.w = fmaf(a1[k], v2[k].w, c1a.w);
                c2a.x = fmaf(a2[k], v1[k].x, c2a.x); c2a.y = fmaf(a2[k], v1[k].y, c2a.y);
                c2a.z = fmaf(a2[k], v1[k].z, c2a.z); c2a.w = fmaf(a2[k], v1[k].w, c2a.w);
            }
        }
        sred[w][lane] = c1a;
        sred[NW + w][lane] = c2a;
        __syncthreads();
        if (tid < 64) {
            int ti = tid >> 5;
            float4 s = sred[ti * NW][lane];
            #pragma unroll
            for (int k = 1; k < NW; k++) {
                float4 v = sred[ti * NW + k][lane];
                s.x += v.x; s.y += v.y; s.z += v.z; s.w += v.w;
            }
            ((float4*)&g_c_part[ti][b][g][0])[lane] = s;
        }
    }
    spin_bar(&g_barG[0], NCTA);      // global: all batches' c + d ready

    // ================= Phase C: logits for ALL batches, own t-chunk ========
    // U is read exactly once chip-wide (each CTA reads its 16 columns).
    {
        for (int i = tid; i < B_ * 2 * E_; i += 1024) {
            int bb = i >> 8, p = (i >> 7) & 1, e = i & 127;
            float acc = 0.f;
            #pragma unroll
            for (int gg = 0; gg < G_; gg++) acc += g_c_part[p][bb][gg][e];
            csh[bb][p][e] = acc * INV_T;
        }
        __syncthreads();

        int bb = tid >> 5;            // batch 0..31 (one warp per batch)
        int p  = (tid >> 4) & 1;      // tensor
        int tt = tid & 15;            // t within chunk
        int t  = ci * CPT + tt;
        const float* U    = p ? U2  : U1;
        const float* bias = p ? bb2 : bb1;
        float acc = 0.f;
        #pragma unroll 8
        for (int e = 0; e < E_; e++)
            acc = fmaf(csh[bb][p][e], __ldg(&U[e * T_ + t]), acc);
        float et = acc + __ldg(&g_d[p][bb][t]) + __ldg(&bias[t]);
        g_et[p][bb][t] = et;
        // 16-lane chunk stats
        float m = et;
        #pragma unroll
        for (int off = 8; off; off >>= 1)
            m = fmaxf(m, __shfl_xor_sync(0xffffffffu, m, off));
        float z = __expf(et - m);
        #pragma unroll
        for (int off = 8; off; off >>= 1)
            z += __shfl_xor_sync(0xffffffffu, z, off);
        if (tt == 0) g_stats[p][bb][ci] = make_float2(m, z);
    }
    spin_bar(&g_barG[1], NCTA);      // global: all logits + stats ready
    __syncthreads();                 // csh -> sred reuse boundary

    // ================= Phase D: softmax weights + weighted sums ============
    if (w < 2) {                     // warp p combines 128 chunk stats
        int p = w;
        float m = -3.4e38f, z = 0.f;
        #pragma unroll
        for (int k = 0; k < 4; k++) {
            float2 st = g_stats[p][b][lane * 4 + k];
            float mn = fmaxf(m, st.x);
            z = z * __expf(m - mn) + st.y * __expf(st.x - mn);
            m = mn;
        }
        #pragma unroll
        for (int off = 16; off; off >>= 1) {
            float mo = __shfl_xor_sync(0xffffffffu, m, off);
            float zo = __shfl_xor_sync(0xffffffffu, z, off);
            float mn = fmaxf(m, mo);
            z = z * __expf(m - mn) + zo * __expf(mo - mn);
            m = mn;
        }
        if (lane == 0) { s_m[p] = m; s_iz[p] = 1.0f / z; }
    }
    __syncthreads();
    {
        int p = tid >> 9, rr = tid & 511;
        tsh[p][rr] = __expf(g_et[p][b][t0 + rr] - s_m[p]) * s_iz[p];
    }
    __syncthreads();
    {
        float4 o1a = {0,0,0,0}, o2a = {0,0,0,0};
        #pragma unroll
        for (int r4 = 0; r4 < RPW; r4 += 4) {
            float4 v1[4], v2[4];
            #pragma unroll
            for (int k = 0; k < 4; k++) {
                v1[k] = __ldg(p1 + (rbase + r4 + k) * 32 + lane);
                v2[k] = __ldg(p2 + (rbase + r4 + k) * 32 + lane);
            }
            #pragma unroll
            for (int k = 0; k < 4; k++) {
                float wt1 = tsh[0][rbase + r4 + k];
                float wt2 = tsh[1][rbase + r4 + k];
                o1a.x = fmaf(wt1, v1[k].x, o1a.x); o1a.y = fmaf(wt1, v1[k].y, o1a.y);
                o1a.z = fmaf(wt1, v1[k].z, o1a.z); o1a.w = fmaf(wt1, v1[k].w, o1a.w);
                o2a.x = fmaf(wt2, v2[k].x, o2a.x); o2a.y = fmaf(wt2, v2[k].y, o2a.y);
                o2a.z = fmaf(wt2, v2[k].z, o2a.z); o2a.w = fmaf(wt2, v2[k].w, o2a.w);
            }
        }
        sred[w][lane] = o1a;
        sred[NW + w][lane] = o2a;
        __syncthreads();
        if (tid < 64) {
            int ti = tid >> 5;
            float4 s = sred[ti * NW][lane];
            #pragma unroll
            for (int k = 1; k < NW; k++) {
                float4 v = sred[ti * NW + k][lane];
                s.x += v.x; s.y += v.y; s.z += v.z; s.w += v.w;
            }
            ((float4*)&g_o_part[ti][b][g][0])[lane] = s;
        }
    }
    spin_bar(&g_barD[b], G_);

    // ---------------- output: CTA g writes its 64 of 256 values ------------
    if (tid < 64) {
        int idx = g * 64 + tid;
        int ti = idx >> 7, e = idx & 127;
        float acc = 0.f;
        #pragma unroll
        for (int gg = 0; gg < G_; gg++) acc += g_o_part[ti][b][gg][e];
        out[b * 256 + idx] = acc;
    }

    // ---------------- cleanup: last CTA resets all counters ----------------
    __syncthreads();
    if (tid == 0) {
        unsigned old = atomicAdd(&g_tick, 1u);
        if (old == NCTA - 1) {
            #pragma unroll
            for (int i = 0; i < B_; i++) { g_barA[i] = 0u; g_barD[i] = 0u; }
            g_barG[0] = 0u;
            g_barG[1] = 0u;
            g_tick = 0u;
        }
    }
}

// ===========================================================================
extern "C" void kernel_launch(void* const* d_in, const int* in_sizes, int n_in,
                              void* d_out, int out_size)
{
    const float* x1 = (const float*)d_in[0];
    const float* x2 = (const float*)d_in[1];
    const float* W1 = (const float*)d_in[2];
    const float* b1 = (const float*)d_in[3];
    const float* U1 = (const float*)d_in[4];
    const float* W2 = (const float*)d_in[5];
    const float* b2 = (const float*)d_in[6];
    const float* U2 = (const float*)d_in[7];
    float* out = (float*)d_out;

    fused_attn<<<NCTA, 1024>>>(x1, x2, W1, b1, U1, W2, b2, U2, out);
}